// round 14
// baseline (speedup 1.0000x reference)
#include <cuda_runtime.h>
#include <math.h>

#define HD 1024
#define VV 50257
#define SS 4096
#define GG 3072        // 3*H
#define GRID_F 148     // front grid: 1 block/SM, guaranteed co-resident
#define GRID_B 740     // back grid: 5 blocks/SM * 148
#define NCH 6283       // ceil(VV / 8) row-chunks

// ---- scratch (no allocations allowed) ----
__device__ float g_gi[GG];
__device__ float g_gh[GG];
__device__ float g_hnew[HD];
__device__ float g_scores[SS];
__device__ float g_logits[VV];
__device__ float g_pm[GRID_B];
__device__ float g_ps[GRID_B];
__device__ unsigned int g_bar = 0;
__device__ unsigned int g_gen = 0;

__device__ __forceinline__ float warp_sum(float v) {
#pragma unroll
    for (int o = 16; o > 0; o >>= 1) v += __shfl_down_sync(0xffffffffu, v, o);
    return v;
}
__device__ __forceinline__ float warp_max(float v) {
#pragma unroll
    for (int o = 16; o > 0; o >>= 1) v = fmaxf(v, __shfl_down_sync(0xffffffffu, v, o));
    return v;
}

// software grid barrier: requires ALL blocks resident (grids sized for that).
__device__ __forceinline__ void grid_barrier(unsigned int nblocks) {
    __threadfence();
    __syncthreads();
    if (threadIdx.x == 0) {
        unsigned int gen = *((volatile unsigned int*)&g_gen);
        unsigned int arr = atomicAdd(&g_bar, 1u);
        if (arr == nblocks - 1u) {
            g_bar = 0u;
            __threadfence();
            atomicAdd(&g_gen, 1u);
        } else {
            while (*((volatile unsigned int*)&g_gen) == gen) __nanosleep(64);
        }
    }
    __syncthreads();
}

// ---------------------------------------------------------------------------
// K_front: gates GEMV -> | -> h_new + scores -> | -> softmax + ctx (col-split)
// 148 blocks x 1024 threads, 1 block/SM.
// ---------------------------------------------------------------------------
__global__ void __launch_bounds__(1024, 1)
k_front(const int* __restrict__ word,
        const float* __restrict__ last_ctx,
        const float* __restrict__ last_hid,
        const float* __restrict__ emb,
        const float* __restrict__ w_ih,
        const float* __restrict__ w_hh,
        const float* __restrict__ b_ih,
        const float* __restrict__ b_hh,
        const float* __restrict__ enc,
        float* __restrict__ o_hn,
        float* __restrict__ o_attn,
        float* __restrict__ o_ctx) {
    __shared__ float sx[2 * HD];
    __shared__ float sh[HD];
    __shared__ float ss[SS];
    __shared__ float sred[32 * 32];
    __shared__ float red[32];

    const int t = threadIdx.x;
    const int lane = t & 31;
    const int wrp  = t >> 5;          // 0..31
    const int b = blockIdx.x;

    // ---------------- phase 1: gates GEMV ----------------
    {
        const int w = word[0];
        sx[t]      = emb[(size_t)w * HD + t];
        sx[HD + t] = last_ctx[t];
        sh[t]      = last_hid[t];
        __syncthreads();

        const int row = b * 32 + wrp;          // 0..4735
        if (row < GG) {
            const float4* wi4 = (const float4*)(w_ih + (size_t)row * 2 * HD);
            const float4* wh4 = (const float4*)(w_hh + (size_t)row * HD);
            const float4* sx4 = (const float4*)sx;
            const float4* sh4 = (const float4*)sh;
            float si = 0.f, sg = 0.f;
#pragma unroll 16
            for (int j = lane; j < 512; j += 32) {
                float4 a = wi4[j], c = sx4[j];
                si += a.x * c.x + a.y * c.y + a.z * c.z + a.w * c.w;
            }
#pragma unroll 8
            for (int j = lane; j < 256; j += 32) {
                float4 a = wh4[j], c = sh4[j];
                sg += a.x * c.x + a.y * c.y + a.z * c.z + a.w * c.w;
            }
            si = warp_sum(si);
            sg = warp_sum(sg);
            if (lane == 0) {
                g_gi[row] = si + b_ih[row];
                g_gh[row] = sg + b_hh[row];
            }
        }
    }
    grid_barrier(GRID_F);

    // ---------------- phase 2: h_new + scores ----------------
    {
        float r  = 1.f / (1.f + expf(-(g_gi[t] + g_gh[t])));
        float z  = 1.f / (1.f + expf(-(g_gi[HD + t] + g_gh[HD + t])));
        float n  = tanhf(g_gi[2 * HD + t] + r * g_gh[2 * HD + t]);
        float hn = (1.f - z) * n + z * sh[t];
        sh[t] = hn;                     // same addr per thread, no race
        if (b == 0) { g_hnew[t] = hn; o_hn[t] = hn; }
        __syncthreads();

        const int s = b * 32 + wrp;     // 0..4735
        if (s < SS) {
            const float4* e4 = (const float4*)(enc + (size_t)s * HD);
            const float4* h4 = (const float4*)sh;
            float acc = 0.f;
#pragma unroll 8
            for (int j = lane; j < 256; j += 32) {
                float4 a = e4[j], c = h4[j];
                acc += a.x * c.x + a.y * c.y + a.z * c.z + a.w * c.w;
            }
            acc = warp_sum(acc);
            if (lane == 0) g_scores[s] = acc;
        }
    }
    grid_barrier(GRID_F);

    // ---------------- phase 3: softmax + ctx (blocks 0..31 only) ----------
    if (b < 32) {
        float4* ss4 = (float4*)ss;
        const float4* gs4 = (const float4*)g_scores;
        float4 v = gs4[t];
        ss4[t] = v;
        float m = fmaxf(fmaxf(v.x, v.y), fmaxf(v.z, v.w));
        m = warp_max(m);
        if (lane == 0) red[wrp] = m;
        __syncthreads();
        if (t < 32) {
            float mm = red[t];
            mm = warp_max(mm);
            if (t == 0) red[0] = mm;
        }
        __syncthreads();
        m = red[0];
        __syncthreads();

        float4 e;
        e.x = expf(v.x - m); e.y = expf(v.y - m);
        e.z = expf(v.z - m); e.w = expf(v.w - m);
        float s = e.x + e.y + e.z + e.w;
        s = warp_sum(s);
        if (lane == 0) red[wrp] = s;
        __syncthreads();
        if (t < 32) {
            float sv = red[t];
            sv = warp_sum(sv);
            if (t == 0) red[0] = sv;
        }
        __syncthreads();
        const float inv = 1.f / red[0];

        float4 a;
        a.x = e.x * inv; a.y = e.y * inv; a.z = e.z * inv; a.w = e.w * inv;
        ss4[t] = a;
        if (b == 0) {   // scalar stores: o_attn (d_out+52305) is not 16B-aligned
            o_attn[4 * t + 0] = a.x;
            o_attn[4 * t + 1] = a.y;
            o_attn[4 * t + 2] = a.z;
            o_attn[4 * t + 3] = a.w;
        }
        __syncthreads();

        // ctx: block b owns cols [b*32, b*32+32); warp w does rows [w*128,+128)
        const int col = b * 32 + lane;
        const float* ecol = enc + col;
        float acc = 0.f;
        const int r0 = wrp * 128;
#pragma unroll 8
        for (int r = r0; r < r0 + 128; r++)
            acc += ss[r] * ecol[(size_t)r * HD];
        sred[wrp * 32 + lane] = acc;
        __syncthreads();

        if (t < 32) {
            float sum = 0.f;
#pragma unroll
            for (int k = 0; k < 32; k++) sum += sred[k * 32 + t];
            o_ctx[b * 32 + t] = sum;
        }
    }
}

// ---------------------------------------------------------------------------
// K_back: persistent logits GEMV with fused online LSE, then output.
// 740 blocks x 256 threads (5/SM, all co-resident).
// ---------------------------------------------------------------------------
__global__ void __launch_bounds__(256, 5)
k_back(const float* __restrict__ out_w,
       const float* __restrict__ out_b,
       const float* __restrict__ o_ctx,
       float* __restrict__ o_out) {
    __shared__ float sx[2 * HD];
    __shared__ float swm[8];
    __shared__ float sws[8];
    __shared__ float red[8];

    const int t = threadIdx.x;
    const int lane = t & 31;
    const int wrp  = t >> 5;            // 0..7

    for (int i = t; i < HD; i += 256) {
        sx[i]      = g_hnew[i];
        sx[HD + i] = o_ctx[i];
    }
    __syncthreads();

    const float4* sx4 = (const float4*)sx;
    float m_loc = -INFINITY, s_loc = 0.f;

    for (int c = blockIdx.x; c < NCH; c += GRID_B) {
        const int row = c * 8 + wrp;
        if (row < VV) {
            const float4* w4 = (const float4*)(out_w + (size_t)row * 2 * HD);
            float acc = 0.f;
#pragma unroll 16
            for (int j = lane; j < 512; j += 32) {
                float4 a = w4[j], x = sx4[j];
                acc += a.x * x.x + a.y * x.y + a.z * x.z + a.w * x.w;
            }
            acc = warp_sum(acc);
            if (lane == 0) {
                float l = acc + out_b[row];
                g_logits[row] = l;
                if (l > m_loc) {                 // online log-sum-exp
                    s_loc = s_loc * expf(m_loc - l) + 1.f;
                    m_loc = l;
                } else {
                    s_loc += expf(l - m_loc);
                }
            }
        }
    }

    if (lane == 0) { swm[wrp] = m_loc; sws[wrp] = s_loc; }
    __syncthreads();
    if (t == 0) {
        float m = -INFINITY, s = 0.f;
#pragma unroll
        for (int k = 0; k < 8; k++) {
            float mk = swm[k], sk = sws[k];
            if (mk > m) { s = s * expf(m - mk) + sk; m = mk; }
            else        { s += sk * expf(mk - m); }
        }
        g_pm[blockIdx.x] = m;
        g_ps[blockIdx.x] = s;
    }

    grid_barrier(GRID_B);

    // every block redundantly combines the 740 partials (4.7 KB, L2)
    float m_l = -INFINITY;
    for (int i = t; i < GRID_B; i += 256) m_l = fmaxf(m_l, g_pm[i]);
    m_l = warp_max(m_l);
    if (lane == 0) red[wrp] = m_l;
    __syncthreads();
    if (t == 0) {
        float mm = -INFINITY;
#pragma unroll
        for (int k = 0; k < 8; k++) mm = fmaxf(mm, red[k]);
        red[0] = mm;
    }
    __syncthreads();
    const float mg = red[0];
    __syncthreads();

    float s_l = 0.f;
    for (int i = t; i < GRID_B; i += 256) s_l += g_ps[i] * expf(g_pm[i] - mg);
    s_l = warp_sum(s_l);
    if (lane == 0) red[wrp] = s_l;
    __syncthreads();
    if (t == 0) {
        float sv = 0.f;
#pragma unroll
        for (int k = 0; k < 8; k++) sv += red[k];
        red[0] = mg + logf(sv);
    }
    __syncthreads();
    const float lse = red[0];

    // strided output write: 740*256 = 189440 >= VV, single pass
    const int i = blockIdx.x * 256 + t;
    if (i < VV) o_out[i] = g_logits[i] - lse;
}

// ---------------------------------------------------------------------------
extern "C" void kernel_launch(void* const* d_in, const int* in_sizes, int n_in,
                              void* d_out, int out_size) {
    const int*   word     = (const int*)  d_in[0];
    const float* last_ctx = (const float*)d_in[1];
    const float* last_hid = (const float*)d_in[2];
    const float* enc      = (const float*)d_in[3];
    const float* emb      = (const float*)d_in[4];
    const float* w_ih     = (const float*)d_in[5];
    const float* w_hh     = (const float*)d_in[6];
    const float* b_ih     = (const float*)d_in[7];
    const float* b_hh     = (const float*)d_in[8];
    const float* out_w    = (const float*)d_in[9];
    const float* out_b    = (const float*)d_in[10];

    float* out    = (float*)d_out;
    float* o_out  = out;                 // [V]   log_softmax output
    float* o_ctx  = out + VV;            // [H]   context
    float* o_hn   = out + VV + HD;       // [H]   h_new
    float* o_attn = out + VV + 2 * HD;   // [S]   attn

    k_front<<<GRID_F, 1024>>>(word, last_ctx, last_hid, emb, w_ih, w_hh,
                              b_ih, b_hh, enc, o_hn, o_attn, o_ctx);
    k_back<<<GRID_B, 256>>>(out_w, out_b, o_ctx, o_out);
}